// round 1
// baseline (speedup 1.0000x reference)
#include <cuda_runtime.h>
#include <math.h>

#define Bx 8
#define Cx 4
#define Hx 384
#define Wx 384
#define SLICE (Hx*Wx)          // 147456
#define NPIX  (Bx*Hx*Wx)       // 1179648
#define NSLICE (Bx*Cx)         // 32
#define BIGV 768.0f            // = H + W, finite sentinel (matches reference)

// Scratch (no cudaMalloc allowed): g2 buffer doubles as dt buffer after phase 2.
__device__ float        g_g2[Bx*Cx*Hx*Wx];   // 18 MB
__device__ unsigned int g_dmax_bits[NSLICE];
__device__ double       g_acc;

// ---------------------------------------------------------------------------
__global__ void k_init() {
    int i = threadIdx.x;
    if (i < NSLICE) g_dmax_bits[i] = 0u;   // dt >= 0, so 0-bits is a valid -inf
    if (i == 0)     g_acc = 0.0;
}

// ---------------------------------------------------------------------------
// Phase 1: vertical 1D distance per (b,c,w) column.
// Backward scan stores g_bwd into scratch; forward scan combines, squares.
// Thread map: w fastest -> coalesced loads/stores across a warp.
__global__ void k_phase1(const int* __restrict__ targets) {
    int tid = blockIdx.x * blockDim.x + threadIdx.x;
    if (tid >= Bx*Cx*Wx) return;
    int w = tid % Wx;
    int c = (tid / Wx) % Cx;
    int b = tid / (Wx * Cx);

    const int* tcol = targets + b * SLICE + w;
    float*     gcol = g_g2 + (b * Cx + c) * SLICE + w;

    float d = BIGV;
    #pragma unroll 4
    for (int h = Hx - 1; h >= 0; --h) {
        int t = tcol[h * Wx];
        d = (t == c) ? 0.0f : fminf(d + 1.0f, BIGV);
        gcol[h * Wx] = d;
    }
    d = BIGV;
    #pragma unroll 4
    for (int h = 0; h < Hx; ++h) {
        int t = tcol[h * Wx];
        d = (t == c) ? 0.0f : fminf(d + 1.0f, BIGV);
        float g = fminf(d, gcol[h * Wx]);
        gcol[h * Wx] = g * g;
    }
}

// ---------------------------------------------------------------------------
// Phase 2: per row (b,c,h): dt(y) = sqrt( min_j g2(j) + (y-j)^2 ).
// Exact pruned outward scan: radii with r^2 >= current_min cannot improve
// the minimum (g2 >= 0), so the scan is mathematically identical to the
// reference brute-force min but terminates after ~g(y) steps.
// One block per row. Overwrites the g2 row with dt in place (shared copy
// holds the inputs). Also accumulates per-slice max via atomicMax on bits.
__global__ void __launch_bounds__(128) k_phase2() {
    __shared__ float s_g2[Wx];
    __shared__ float s_red[4];

    int row   = blockIdx.x;        // 0 .. B*C*H-1
    int slice = row / Hx;          // b*C + c
    float* grow = g_g2 + (size_t)row * Wx;

    for (int i = threadIdx.x; i < Wx; i += blockDim.x) s_g2[i] = grow[i];
    __syncthreads();

    float lmax = 0.0f;
    #pragma unroll
    for (int k = 0; k < Wx / 128; ++k) {
        int y = threadIdx.x + k * 128;
        float m = s_g2[y];
        int r = 1;
        while (r < Wx) {
            float r2 = (float)(r * r);
            if (r2 >= m) break;
            int jl = y - r, jr = y + r;
            if (jl >= 0) m = fminf(m, s_g2[jl] + r2);
            if (jr < Wx) m = fminf(m, s_g2[jr] + r2);
            ++r;
        }
        float dt = sqrtf(m);
        lmax = fmaxf(lmax, dt);
        grow[y] = dt;              // safe: readers use shared copy only
    }

    // block max -> atomicMax on float bits (valid: all values >= 0)
    #pragma unroll
    for (int off = 16; off > 0; off >>= 1)
        lmax = fmaxf(lmax, __shfl_down_sync(0xffffffffu, lmax, off));
    int wid = threadIdx.x >> 5;
    if ((threadIdx.x & 31) == 0) s_red[wid] = lmax;
    __syncthreads();
    if (threadIdx.x == 0) {
        float bm = fmaxf(fmaxf(s_red[0], s_red[1]), fmaxf(s_red[2], s_red[3]));
        atomicMax(&g_dmax_bits[slice], __float_as_uint(bm));
    }
}

// ---------------------------------------------------------------------------
// Phase 3: per pixel softmax over C=4, dot with dist_map, f64 accumulation.
__global__ void __launch_bounds__(256) k_phase3(const float* __restrict__ outputs,
                                                const int*   __restrict__ targets) {
    int idx = blockIdx.x * blockDim.x + threadIdx.x;  // over B*H*W
    double local = 0.0;
    if (idx < NPIX) {
        int b  = idx / SLICE;
        int hw = idx - b * SLICE;
        int t  = targets[idx];

        const float* o = outputs + (size_t)b * Cx * SLICE + hw;
        float l0 = o[0];
        float l1 = o[SLICE];
        float l2 = o[2 * SLICE];
        float l3 = o[3 * SLICE];
        float mx = fmaxf(fmaxf(l0, l1), fmaxf(l2, l3));
        float e0 = expf(l0 - mx);
        float e1 = expf(l1 - mx);
        float e2 = expf(l2 - mx);
        float e3 = expf(l3 - mx);
        float inv = 1.0f / (e0 + e1 + e2 + e3);

        const float* dtp = g_g2 + (size_t)b * Cx * SLICE + hw;
        float d0 = (t == 0) ? -__uint_as_float(g_dmax_bits[b * Cx + 0]) : dtp[0];
        float d1 = (t == 1) ? -__uint_as_float(g_dmax_bits[b * Cx + 1]) : dtp[SLICE];
        float d2 = (t == 2) ? -__uint_as_float(g_dmax_bits[b * Cx + 2]) : dtp[2 * SLICE];
        float d3 = (t == 3) ? -__uint_as_float(g_dmax_bits[b * Cx + 3]) : dtp[3 * SLICE];

        float acc = e0 * d0 + e1 * d1 + e2 * d2 + e3 * d3;
        local = (double)acc * (double)inv;
    }
    #pragma unroll
    for (int off = 16; off > 0; off >>= 1)
        local += __shfl_down_sync(0xffffffffu, local, off);
    if ((threadIdx.x & 31) == 0)
        atomicAdd(&g_acc, local);
}

// ---------------------------------------------------------------------------
__global__ void k_final(float* __restrict__ out) {
    // mean over B*C*H*W elements, each term already divided by C
    out[0] = (float)(g_acc / ((double)Cx * (double)Bx * Cx * Hx * Wx));
}

// ---------------------------------------------------------------------------
extern "C" void kernel_launch(void* const* d_in, const int* in_sizes, int n_in,
                              void* d_out, int out_size) {
    const float* outputs = (const float*)d_in[0];
    const int*   targets = (const int*)d_in[1];
    float*       out     = (float*)d_out;

    k_init<<<1, 32>>>();
    k_phase1<<<(Bx * Cx * Wx) / 384, 384>>>(targets);
    k_phase2<<<Bx * Cx * Hx, 128>>>();
    k_phase3<<<(NPIX + 255) / 256, 256>>>(outputs, targets);
    k_final<<<1, 1>>>(out);
}

// round 2
// speedup vs baseline: 2.5134x; 2.5134x over previous
#include <cuda_runtime.h>
#include <math.h>

#define Bx 8
#define Cx 4
#define Hx 384
#define Wx 384
#define SLICE (Hx*Wx)          // 147456
#define NPIX  (Bx*Hx*Wx)       // 1179648
#define NSLICE (Bx*Cx)         // 32
#define BIGI 768               // = H + W, finite sentinel (matches reference)

// Scratch (no cudaMalloc allowed): g2 buffer doubles as dt buffer after phase 2.
__device__ float        g_g2[Bx*Cx*Hx*Wx];   // 18 MB
__device__ unsigned int g_dmax_bits[NSLICE];
__device__ double       g_acc;

// ---------------------------------------------------------------------------
__global__ void k_init() {
    int i = threadIdx.x;
    if (i < NSLICE) g_dmax_bits[i] = 0u;   // dt >= 0, so 0-bits is a valid -inf
    if (i == 0)     g_acc = 0.0;
}

// ---------------------------------------------------------------------------
// Phase 1: vertical 1D distance per (b,c,w) column, squared.
// One warp per (b, c, 32-column tile). Targets tile bulk-loaded to shared
// (int4, high MLP); both scans then run out of shared, so the sequential
// h-loop is ALU/LDS-bound instead of global-latency-bound. Backward scan
// buffered in shared u16; forward scan combines and writes g^2 once.
__global__ void __launch_bounds__(32) k_phase1(const int* __restrict__ targets) {
    __shared__ unsigned char  s_t[Hx * 32];   // 12 KB: target labels (0..3)
    __shared__ unsigned short s_b[Hx * 32];   // 24 KB: backward distances

    int blk = blockIdx.x;                 // 0 .. B*C*(W/32)-1
    int wt  = blk % (Wx / 32);
    int c   = (blk / (Wx / 32)) & 3;
    int b   = blk / (4 * (Wx / 32));
    int w0  = wt * 32;
    int lane = threadIdx.x;

    // Bulk load the 384x32 target tile (int4 = 16B per lane per iter).
    const int4* tp = (const int4*)(targets + (size_t)b * SLICE + w0);
    #pragma unroll 8
    for (int i = lane; i < Hx * 8; i += 32) {
        int h = i >> 3, q = i & 7;
        int4 v = __ldg(&tp[h * (Wx / 4) + q]);
        int base = h * 32 + q * 4;
        s_t[base + 0] = (unsigned char)v.x;
        s_t[base + 1] = (unsigned char)v.y;
        s_t[base + 2] = (unsigned char)v.z;
        s_t[base + 3] = (unsigned char)v.w;
    }
    __syncwarp();

    // Backward scan (h descending)
    int d = BIGI;
    #pragma unroll 4
    for (int h = Hx - 1; h >= 0; --h) {
        bool z = (s_t[h * 32 + lane] == (unsigned char)c);
        d = z ? 0 : min(d + 1, BIGI);
        s_b[h * 32 + lane] = (unsigned short)d;
    }

    // Forward scan + combine + square -> global (coalesced 128B per warp)
    d = BIGI;
    float* gout = g_g2 + ((size_t)(b * Cx + c)) * SLICE + w0 + lane;
    #pragma unroll 4
    for (int h = 0; h < Hx; ++h) {
        bool z = (s_t[h * 32 + lane] == (unsigned char)c);
        d = z ? 0 : min(d + 1, BIGI);
        int g = min(d, (int)s_b[h * 32 + lane]);
        gout[h * Wx] = (float)(g * g);   // < 2^24, exact in f32
    }
}

// ---------------------------------------------------------------------------
// Phase 2: per row (b,c,h): dt(y) = sqrt( min_j g2(j) + (y-j)^2 ).
// Exact pruned outward scan: any radius with r^2 >= current running min
// cannot improve it (g2 >= 0) -> identical result to brute-force min.
__global__ void __launch_bounds__(128) k_phase2() {
    __shared__ float s_g2[Wx];
    __shared__ float s_red[4];

    int row   = blockIdx.x;        // 0 .. B*C*H-1
    int slice = row / Hx;          // b*C + c
    float* grow = g_g2 + (size_t)row * Wx;

    for (int i = threadIdx.x; i < Wx; i += blockDim.x) s_g2[i] = grow[i];
    __syncthreads();

    float lmax = 0.0f;
    #pragma unroll
    for (int k = 0; k < Wx / 128; ++k) {
        int y = threadIdx.x + k * 128;
        float m = s_g2[y];
        int r = 1;
        while (r < Wx) {
            float r2 = (float)(r * r);
            if (r2 >= m) break;
            int jl = y - r, jr = y + r;
            if (jl >= 0) m = fminf(m, s_g2[jl] + r2);
            if (jr < Wx) m = fminf(m, s_g2[jr] + r2);
            ++r;
        }
        float dt = sqrtf(m);
        lmax = fmaxf(lmax, dt);
        grow[y] = dt;              // safe: readers use the shared copy only
    }

    // block max -> atomicMax on float bits (valid: all values >= 0)
    #pragma unroll
    for (int off = 16; off > 0; off >>= 1)
        lmax = fmaxf(lmax, __shfl_down_sync(0xffffffffu, lmax, off));
    int wid = threadIdx.x >> 5;
    if ((threadIdx.x & 31) == 0) s_red[wid] = lmax;
    __syncthreads();
    if (threadIdx.x == 0) {
        float bm = fmaxf(fmaxf(s_red[0], s_red[1]), fmaxf(s_red[2], s_red[3]));
        atomicMax(&g_dmax_bits[slice], __float_as_uint(bm));
    }
}

// ---------------------------------------------------------------------------
// Phase 3: per pixel softmax over C=4 dotted with dist_map.
// 4 pixels per thread via 16B vector loads (high MLP); f32 per-thread
// accumulation, f64 warp/block reduce, ONE f64 atomic per block.
__device__ __forceinline__ float pix_term(float l0, float l1, float l2, float l3,
                                          float d0, float d1, float d2, float d3,
                                          int t, float m0, float m1, float m2, float m3) {
    float mx = fmaxf(fmaxf(l0, l1), fmaxf(l2, l3));
    float e0 = __expf(l0 - mx);
    float e1 = __expf(l1 - mx);
    float e2 = __expf(l2 - mx);
    float e3 = __expf(l3 - mx);
    float inv = 1.0f / (e0 + e1 + e2 + e3);
    d0 = (t == 0) ? m0 : d0;
    d1 = (t == 1) ? m1 : d1;
    d2 = (t == 2) ? m2 : d2;
    d3 = (t == 3) ? m3 : d3;
    return (e0 * d0 + e1 * d1 + e2 * d2 + e3 * d3) * inv;
}

__global__ void __launch_bounds__(256) k_phase3(const float* __restrict__ outputs,
                                                const int*   __restrict__ targets) {
    int tid  = blockIdx.x * 256 + threadIdx.x;   // NPIX/4 threads exactly
    int base = tid * 4;
    int b  = base / SLICE;
    int hw = base - b * SLICE;

    int4 t4 = *(const int4*)(targets + base);

    const float* ob = outputs + (size_t)b * Cx * SLICE + hw;
    float4 L0 = *(const float4*)(ob);
    float4 L1 = *(const float4*)(ob + SLICE);
    float4 L2 = *(const float4*)(ob + 2 * SLICE);
    float4 L3 = *(const float4*)(ob + 3 * SLICE);

    const float* db = g_g2 + (size_t)b * Cx * SLICE + hw;
    float4 D0 = *(const float4*)(db);
    float4 D1 = *(const float4*)(db + SLICE);
    float4 D2 = *(const float4*)(db + 2 * SLICE);
    float4 D3 = *(const float4*)(db + 3 * SLICE);

    float m0 = -__uint_as_float(g_dmax_bits[b * Cx + 0]);
    float m1 = -__uint_as_float(g_dmax_bits[b * Cx + 1]);
    float m2 = -__uint_as_float(g_dmax_bits[b * Cx + 2]);
    float m3 = -__uint_as_float(g_dmax_bits[b * Cx + 3]);

    float accf = 0.0f;
    accf += pix_term(L0.x, L1.x, L2.x, L3.x, D0.x, D1.x, D2.x, D3.x, t4.x, m0, m1, m2, m3);
    accf += pix_term(L0.y, L1.y, L2.y, L3.y, D0.y, D1.y, D2.y, D3.y, t4.y, m0, m1, m2, m3);
    accf += pix_term(L0.z, L1.z, L2.z, L3.z, D0.z, D1.z, D2.z, D3.z, t4.z, m0, m1, m2, m3);
    accf += pix_term(L0.w, L1.w, L2.w, L3.w, D0.w, D1.w, D2.w, D3.w, t4.w, m0, m1, m2, m3);

    double v = (double)accf;
    #pragma unroll
    for (int off = 16; off > 0; off >>= 1)
        v += __shfl_down_sync(0xffffffffu, v, off);

    __shared__ double sred[8];
    int wid = threadIdx.x >> 5;
    if ((threadIdx.x & 31) == 0) sred[wid] = v;
    __syncthreads();
    if (threadIdx.x == 0) {
        double s = 0.0;
        #pragma unroll
        for (int i = 0; i < 8; ++i) s += sred[i];
        atomicAdd(&g_acc, s);
    }
}

// ---------------------------------------------------------------------------
__global__ void k_final(float* __restrict__ out) {
    // mean over B*C*H*W elements, each term already divided by C
    out[0] = (float)(g_acc / ((double)Cx * (double)Bx * Cx * Hx * Wx));
}

// ---------------------------------------------------------------------------
extern "C" void kernel_launch(void* const* d_in, const int* in_sizes, int n_in,
                              void* d_out, int out_size) {
    const float* outputs = (const float*)d_in[0];
    const int*   targets = (const int*)d_in[1];
    float*       out     = (float*)d_out;

    k_init<<<1, 32>>>();
    k_phase1<<<Bx * Cx * (Wx / 32), 32>>>(targets);
    k_phase2<<<Bx * Cx * Hx, 128>>>();
    k_phase3<<<NPIX / 4 / 256, 256>>>(outputs, targets);
    k_final<<<1, 1>>>(out);
}